// round 13
// baseline (speedup 1.0000x reference)
#include <cuda_runtime.h>
#include <mma.h>

using namespace nvcuda;

#define NN 100000
#define EE 600000
#define IND 12
#define HD  128
#define NL  3
#define BNEPS 1e-5f
#define SCB 1024
#define NSCAN ((NN + SCB - 1) / SCB)   // 98

// ---------------- device scratch (static, no allocation) ----------------
// GB300 fabric-init (802) flake rate grows with static size: keep minimal.
// src/dst alias into g_buf1 (dead until gemm12); cursor aliases into
// g_buf0 past the msg12 region (dead until gather12).
__device__ float g_buf0[NN * HD];
__device__ float g_buf1[NN * HD];
__device__ int   g_adj[EE];
__device__ int   g_rowptr[NN + 1];
__device__ int   g_deg[NN];
__device__ float g_invdeg[NN];
__device__ int   g_bsum[NSCAN];
__device__ float g_W1c[IND * HD];
__device__ float g_W2c[IND * HD];
__device__ float g_bias1[HD];
__device__ float g_biasd[HD];
__device__ float g_sum[HD];
__device__ float g_sqsum[HD];
__device__ float g_bnsc[2][HD];
__device__ float g_bnsh[2][HD];
__device__ int   g_is64;

__device__ __forceinline__ float* selbuf(int s) { return s ? g_buf1 : g_buf0; }
__device__ __forceinline__ int* srcp() { return (int*)g_buf1; }
__device__ __forceinline__ int* dstp() { return ((int*)g_buf1) + EE; }
__device__ __forceinline__ int* curp() { return (int*)(g_buf0 + (size_t)NN * IND); }

// ---------------- dtype detection ----------------
__global__ void detect_dtype_kernel(const void* p) {
    const int* pi = (const int*)p;
    int nz = 0;
    for (int k = threadIdx.x; k < 256; k += blockDim.x)
        nz |= (pi[2 * k + 1] != 0);
    nz = __syncthreads_or(nz);
    if (threadIdx.x == 0) g_is64 = nz ? 0 : 1;
}

// extract edges + zero deg + zero folded-weight accumulators
__global__ void extract_edges_kernel(const void* p) {
    int i = blockIdx.x * blockDim.x + threadIdx.x;
    if (i < NN) g_deg[i] = 0;
    if (i < IND * HD) { g_W1c[i] = 0.f; g_W2c[i] = 0.f; }
    if (i < HD) { g_bias1[i] = 0.f; g_biasd[i] = 0.f; }
    if (i >= 2 * EE) return;
    int v;
    if (g_is64) v = (int)((const long long*)p)[i];
    else        v = ((const int*)p)[i];
    if (i < EE) srcp()[i] = v;
    else        dstp()[i - EE] = v;
}

__global__ void count_deg_kernel() {
    int e = blockIdx.x * blockDim.x + threadIdx.x;
    if (e < EE) atomicAdd(&g_deg[dstp()[e]], 1);
}

// ---------------- layer-1 folded weights, parallel over K-chunks --------
__global__ void prep_weights_kernel(const float* __restrict__ embW,
                                    const float* __restrict__ emb_b,
                                    const float* __restrict__ Ws,
                                    const float* __restrict__ Wn,
                                    const float* __restrict__ cb) {
    int c = threadIdx.x;
    int k = blockIdx.x;             // 0..12 (12 = bias row)
    int j0 = blockIdx.y * 32;
    const float* v = (k < IND) ? (embW + k * HD) : emb_b;
    float a0 = 0.f, a1 = 0.f, a2 = 0.f, a3 = 0.f;
    float b0 = 0.f, b1v = 0.f, b2v = 0.f, b3 = 0.f;
#pragma unroll
    for (int j = j0; j < j0 + 32; j += 4) {
        float e0 = __ldg(&v[j + 0]), e1 = __ldg(&v[j + 1]);
        float e2 = __ldg(&v[j + 2]), e3 = __ldg(&v[j + 3]);
        a0 += e0 * __ldg(&Ws[(j + 0) * HD + c]);
        a1 += e1 * __ldg(&Ws[(j + 1) * HD + c]);
        a2 += e2 * __ldg(&Ws[(j + 2) * HD + c]);
        a3 += e3 * __ldg(&Ws[(j + 3) * HD + c]);
        b0  += e0 * __ldg(&Wn[(j + 0) * HD + c]);
        b1v += e1 * __ldg(&Wn[(j + 1) * HD + c]);
        b2v += e2 * __ldg(&Wn[(j + 2) * HD + c]);
        b3  += e3 * __ldg(&Wn[(j + 3) * HD + c]);
    }
    float ra = (a0 + a1) + (a2 + a3);
    float rb = (b0 + b1v) + (b2v + b3);
    if (k < IND) {
        atomicAdd(&g_W1c[k * HD + c], ra);
        atomicAdd(&g_W2c[k * HD + c], rb);
    } else {
        atomicAdd(&g_bias1[c], ra + (blockIdx.y == 0 ? __ldg(&cb[c]) : 0.f));
        atomicAdd(&g_biasd[c], rb);
    }
}

// ---------------- parallel CSR scan -------------------------------------
__global__ void blocksum_kernel() {          // <<<NSCAN, SCB>>>
    __shared__ int wsum[32];
    int i = blockIdx.x * SCB + threadIdx.x;
    int v = (i < NN) ? g_deg[i] : 0;
    int lane = threadIdx.x & 31, wid = threadIdx.x >> 5;
#pragma unroll
    for (int off = 16; off; off >>= 1) v += __shfl_down_sync(0xffffffffu, v, off);
    if (lane == 0) wsum[wid] = v;
    __syncthreads();
    if (wid == 0) {
        int t = (lane < 32) ? wsum[lane] : 0;
#pragma unroll
        for (int off = 16; off; off >>= 1) t += __shfl_down_sync(0xffffffffu, t, off);
        if (lane == 0) g_bsum[blockIdx.x] = t;
    }
}
__global__ void scan_bsum_kernel() {         // <<<1, 128>>>  (+BN sum init)
    __shared__ int vals[NSCAN];
    int tid = threadIdx.x;
    if (tid < HD) { g_sum[tid] = 0.f; g_sqsum[tid] = 0.f; }
    if (tid < NSCAN) vals[tid] = g_bsum[tid];
    __syncthreads();
    if (tid == 0) {
        int acc = 0;
        for (int k = 0; k < NSCAN; k++) { int t = vals[k]; vals[k] = acc; acc += t; }
        g_rowptr[NN] = acc;
    }
    __syncthreads();
    if (tid < NSCAN) g_bsum[tid] = vals[tid];
}
__global__ void fill_rowptr_kernel() {       // <<<NSCAN, SCB>>>  (+invdeg)
    __shared__ int wsum[32];
    int i = blockIdx.x * SCB + threadIdx.x;
    int lane = threadIdx.x & 31, wid = threadIdx.x >> 5;
    int v = (i < NN) ? g_deg[i] : 0;
    int inc = v;
#pragma unroll
    for (int off = 1; off < 32; off <<= 1) {
        int t = __shfl_up_sync(0xffffffffu, inc, off);
        if (lane >= off) inc += t;
    }
    if (lane == 31) wsum[wid] = inc;
    __syncthreads();
    if (wid == 0) {
        int wi = wsum[lane];
#pragma unroll
        for (int off = 1; off < 32; off <<= 1) {
            int t = __shfl_up_sync(0xffffffffu, wi, off);
            if (lane >= off) wi += t;
        }
        wsum[lane] = wi;
    }
    __syncthreads();
    int excl = inc - v + (wid ? wsum[wid - 1] : 0) + g_bsum[blockIdx.x];
    if (i < NN) {
        curp()[i] = excl;
        g_rowptr[i] = excl;
        g_invdeg[i] = 1.f / fmaxf((float)v, 1.f);
    }
}

__global__ void place_edges_kernel() {
    int e = blockIdx.x * blockDim.x + threadIdx.x;
    if (e >= EE) return;
    int d = dstp()[e];
    int pos = atomicAdd(&curp()[d], 1);
    g_adj[pos] = srcp()[e];
}

// ---------------- layer-1 gather in 12-dim feature space ---------------
__global__ void gather12_kernel(const float* __restrict__ F) {
    float* __restrict__ msg12 = g_buf0;   // alias
    int gid = blockIdx.x * blockDim.x + threadIdx.x;
    int node = gid >> 2, ch = gid & 3;
    if (node >= NN || ch >= 3) return;
    int beg = __ldg(&g_rowptr[node]);
    int end = __ldg(&g_rowptr[node + 1]);
    float4 acc = make_float4(0.f, 0.f, 0.f, 0.f);
    for (int j = beg; j < end; j++) {
        int s = __ldg(&g_adj[j]);
        float4 v = __ldg((const float4*)(F + (size_t)s * IND) + ch);
        acc.x += v.x; acc.y += v.y; acc.z += v.z; acc.w += v.w;
    }
    float sc = g_invdeg[node];
    acc.x *= sc; acc.y *= sc; acc.z *= sc; acc.w *= sc;
    *(float4*)(msg12 + (size_t)node * IND + ch * 4) = acc;
}

// ---------------- layer-1 GEMM (K=12, fp32 FFMA) -> buf1 raw1 ----------
#define G12NB 8
__global__ void __launch_bounds__(128)
gemm12_kernel(const float* __restrict__ F) {
    const float* __restrict__ msg12 = g_buf0;  // alias
    __shared__ float W1s[IND * HD], W2s[IND * HD];
    __shared__ float Fs[G12NB][IND], Ms[G12NB][IND];
    int c = threadIdx.x;
    for (int i = c; i < IND * HD; i += 128) { W1s[i] = g_W1c[i]; W2s[i] = g_W2c[i]; }
    float bfx = g_bias1[c], bdg = g_biasd[c];
    int nrow_off = c / IND, kk = c % IND;
    float s = 0.f, s2 = 0.f;
    float* C = g_buf1;
    for (int base = blockIdx.x * G12NB; base < NN; base += gridDim.x * G12NB) {
        __syncthreads();
        if (c < 8 * IND) {
            int n = base + nrow_off;
            Fs[nrow_off][kk] = (n < NN) ? __ldg(&F[(size_t)n * IND + kk]) : 0.f;
            Ms[nrow_off][kk] = (n < NN) ? msg12[(size_t)n * IND + kk] : 0.f;
        }
        __syncthreads();
#pragma unroll
        for (int r = 0; r < G12NB; r++) {
            int n = base + r;
            if (n >= NN) break;
            float acc = bfx + (__ldg(&g_deg[n]) ? bdg : 0.f);
#pragma unroll
            for (int k = 0; k < IND; k++)
                acc += Fs[r][k] * W1s[k * HD + c] + Ms[r][k] * W2s[k * HD + c];
            C[(size_t)n * HD + c] = acc;
            s += acc; s2 += acc * acc;
        }
    }
    atomicAdd(&g_sum[c], s);
    atomicAdd(&g_sqsum[c], s2);
}

// ---------------- fused GATHER+dual GEMM (tf32, BK=16) ------------------
//   C = act(H) @ Wself + [invdeg * Σ_adj act(H)] @ Wneigh + bias.
//   Pass 1's A-tile is built by in-kernel CSR gather (msg never
//   materialized). Reads ONLY selbuf(hsel); writes ONLY selbuf(hsel^1).
//   act = BN+ReLU (slot bnslot) if bnslot>=0, identity otherwise.
#define BM 128
#define BK 16
#define ALD (BK + 4)
#define BLD (HD + 4)
#define WTLD 20
__global__ void __launch_bounds__(256)
gemm_fused_kernel(int hsel, int bnslot,
                  const float* __restrict__ Wsp,
                  const float* __restrict__ Wnp,
                  const float* __restrict__ bias) {
    __shared__ float As[BM * ALD];
    __shared__ float Bs[BK * BLD];
    __shared__ float wtile[8][16 * WTLD];
    __shared__ float colsum[HD], colsq[HD];
    __shared__ float bsc[HD], bsh[HD];

    const float* H = selbuf(hsel);
    float* C = selbuf(hsel ^ 1);
    const int nrows = NN;
    int tid = threadIdx.x;
    int w = tid >> 5, lane = tid & 31;
    int wm = w & 3, wn = w >> 2;
    int row0 = blockIdx.x * BM;

    if (tid < HD) {
        colsum[tid] = 0.f; colsq[tid] = 0.f;
        if (bnslot >= 0) { bsc[tid] = g_bnsc[bnslot][tid]; bsh[tid] = g_bnsh[bnslot][tid]; }
    }

    // row/CSR info for this thread's gather row (pass 1): 2 threads per row
    int gm = tid >> 1, ghalf = tid & 1;
    int grow = row0 + gm;
    int grc = grow < nrows ? grow : nrows - 1;
    int gbeg = __ldg(&g_rowptr[grc]);
    int gend = __ldg(&g_rowptr[grc + 1]);
    float ginv = g_invdeg[grc];

    wmma::fragment<wmma::accumulator, 16, 16, 8, float> acc[2][4];
#pragma unroll
    for (int i = 0; i < 2; i++)
#pragma unroll
        for (int j = 0; j < 4; j++) wmma::fill_fragment(acc[i][j], 0.f);

    for (int pass = 0; pass < 2; ++pass) {
        const float* W = pass ? Wnp : Wsp;
        for (int k0 = 0; k0 < HD; k0 += BK) {
            __syncthreads();
            if (pass == 0) {
                // coalesced self A-tile (optional act)
#pragma unroll
                for (int q = 0; q < 2; q++) {
                    int idx = tid * 2 + q;
                    int m = idx >> 2;
                    int kk = (idx & 3) * 4;
                    int row = row0 + m;
                    int rc = row < nrows ? row : nrows - 1;
                    float4 v = __ldg((const float4*)(H + (size_t)rc * HD + k0 + kk));
                    if (bnslot >= 0) {
                        v.x = fmaxf(v.x * bsc[k0 + kk + 0] + bsh[k0 + kk + 0], 0.f);
                        v.y = fmaxf(v.y * bsc[k0 + kk + 1] + bsh[k0 + kk + 1], 0.f);
                        v.z = fmaxf(v.z * bsc[k0 + kk + 2] + bsh[k0 + kk + 2], 0.f);
                        v.w = fmaxf(v.w * bsc[k0 + kk + 3] + bsh[k0 + kk + 3], 0.f);
                    }
                    As[m * ALD + kk + 0] = wmma::__float_to_tf32(v.x);
                    As[m * ALD + kk + 1] = wmma::__float_to_tf32(v.y);
                    As[m * ALD + kk + 2] = wmma::__float_to_tf32(v.z);
                    As[m * ALD + kk + 3] = wmma::__float_to_tf32(v.w);
                }
            } else {
                // gathered neighbor A-tile: each thread owns row gm, 8 cols
                int cb0 = k0 + ghalf * 8;
                float4 a0 = make_float4(0.f, 0.f, 0.f, 0.f);
                float4 a1 = make_float4(0.f, 0.f, 0.f, 0.f);
                if (bnslot >= 0) {
                    float s0 = bsc[cb0+0], s1 = bsc[cb0+1], s2 = bsc[cb0+2], s3 = bsc[cb0+3];
                    float s4 = bsc[cb0+4], s5 = bsc[cb0+5], s6 = bsc[cb0+6], s7 = bsc[cb0+7];
                    float h0 = bsh[cb0+0], h1 = bsh[cb0+1], h2 = bsh[cb0+2], h3 = bsh[cb0+3];
                    float h4 = bsh[cb0+4], h5 = bsh[cb0+5], h6 = bsh[cb0+6], h7 = bsh[cb0+7];
                    for (int j = gbeg; j < gend; j++) {
                        int s = __ldg(&g_adj[j]);
                        const float4* p = (const float4*)(H + (size_t)s * HD + cb0);
                        float4 va = __ldg(p), vb = __ldg(p + 1);
                        a0.x += fmaxf(va.x * s0 + h0, 0.f);
                        a0.y += fmaxf(va.y * s1 + h1, 0.f);
                        a0.z += fmaxf(va.z * s2 + h2, 0.f);
                        a0.w += fmaxf(va.w * s3 + h3, 0.f);
                        a1.x += fmaxf(vb.x * s4 + h4, 0.f);
                        a1.y += fmaxf(vb.y * s5 + h5, 0.f);
                        a1.z += fmaxf(vb.z * s6 + h6, 0.f);
                        a1.w += fmaxf(vb.w * s7 + h7, 0.f);
                    }
                } else {
                    for (int j = gbeg; j < gend; j++) {
                        int s = __ldg(&g_adj[j]);
                        const float4* p = (const float4*)(H + (size_t)s * HD + cb0);
                        float4 va = __ldg(p), vb = __ldg(p + 1);
                        a0.x += va.x; a0.y += va.y; a0.z += va.z; a0.w += va.w;
                        a1.x += vb.x; a1.y += vb.y; a1.z += vb.z; a1.w += vb.w;
                    }
                }
                float* dst = &As[gm * ALD + ghalf * 8];
                dst[0] = wmma::__float_to_tf32(a0.x * ginv);
                dst[1] = wmma::__float_to_tf32(a0.y * ginv);
                dst[2] = wmma::__float_to_tf32(a0.z * ginv);
                dst[3] = wmma::__float_to_tf32(a0.w * ginv);
                dst[4] = wmma::__float_to_tf32(a1.x * ginv);
                dst[5] = wmma::__float_to_tf32(a1.y * ginv);
                dst[6] = wmma::__float_to_tf32(a1.z * ginv);
                dst[7] = wmma::__float_to_tf32(a1.w * ginv);
            }
            // W tile: 16 rows x 128 cols
#pragma unroll
            for (int q = 0; q < 2; q++) {
                int idx = tid * 2 + q;
                int kk = idx >> 5;
                int c4 = idx & 31;
                float4 v = __ldg((const float4*)(W + (size_t)(k0 + kk) * HD + c4 * 4));
                Bs[kk * BLD + c4 * 4 + 0] = wmma::__float_to_tf32(v.x);
                Bs[kk * BLD + c4 * 4 + 1] = wmma::__float_to_tf32(v.y);
                Bs[kk * BLD + c4 * 4 + 2] = wmma::__float_to_tf32(v.z);
                Bs[kk * BLD + c4 * 4 + 3] = wmma::__float_to_tf32(v.w);
            }
            __syncthreads();
#pragma unroll
            for (int ks = 0; ks < BK; ks += 8) {
                wmma::fragment<wmma::matrix_a, 16, 16, 8, wmma::precision::tf32, wmma::row_major> af[2];
                wmma::fragment<wmma::matrix_b, 16, 16, 8, wmma::precision::tf32, wmma::row_major> bf[4];
#pragma unroll
                for (int i = 0; i < 2; i++)
                    wmma::load_matrix_sync(af[i], &As[(wm * 32 + i * 16) * ALD + ks], ALD);
#pragma unroll
                for (int j = 0; j < 4; j++)
                    wmma::load_matrix_sync(bf[j], &Bs[ks * BLD + wn * 64 + j * 16], BLD);
#pragma unroll
                for (int i = 0; i < 2; i++)
#pragma unroll
                    for (int j = 0; j < 4; j++)
                        wmma::mma_sync(acc[i][j], af[i], bf[j], acc[i][j]);
            }
        }
    }

    float* wt = wtile[w];
    int cl = lane & 15;
    int rh = lane >> 4;
#pragma unroll
    for (int i = 0; i < 2; i++) {
#pragma unroll
        for (int j = 0; j < 4; j++) {
            wmma::store_matrix_sync(wt, acc[i][j], WTLD, wmma::mem_row_major);
            __syncwarp();
            int gc = wn * 64 + j * 16 + cl;
            int rbase = row0 + wm * 32 + i * 16 + rh * 8;
            float bia = bias[gc];
            float s = 0.f, s2 = 0.f;
#pragma unroll
            for (int r = 0; r < 8; r++) {
                int gr = rbase + r;
                float v = wt[(rh * 8 + r) * WTLD + cl] + bia;
                if (gr < nrows) {
                    C[(size_t)gr * HD + gc] = v;
                    s += v;
                    s2 += v * v;
                }
            }
            s  += __shfl_down_sync(0xffffffffu, s, 16);
            s2 += __shfl_down_sync(0xffffffffu, s2, 16);
            if (lane < 16) {
                atomicAdd(&colsum[gc], s);
                atomicAdd(&colsq[gc], s2);
            }
            __syncwarp();
        }
    }
    __syncthreads();
    if (tid < HD) {
        atomicAdd(&g_sum[tid], colsum[tid]);
        atomicAdd(&g_sqsum[tid], colsq[tid]);
    }
}

// ---------------- BN finalize into slot (+self-reset) ------------------
__global__ void bn_finalize_kernel(const float* __restrict__ gamma,
                                   const float* __restrict__ beta, int slot) {
    int c = threadIdx.x;
    float mu = g_sum[c] * (1.0f / NN);
    float var = g_sqsum[c] * (1.0f / NN) - mu * mu;
    float r = rsqrtf(var + BNEPS);
    float a = gamma[c] * r;
    g_bnsc[slot][c] = a;
    g_bnsh[slot][c] = beta[c] - mu * a;
    g_sum[c] = 0.f;
    g_sqsum[c] = 0.f;
}

// ---------------- layer-2 act: h2 = relu(bn1(raw2)) + relu(bn0(raw1)) --
__global__ void bn_apply2_kernel() {
    float* X = g_buf0;                // raw2 -> h2 (in place)
    const float* Res = g_buf1;        // raw1
    int i = blockIdx.x * blockDim.x + threadIdx.x;
    int total4 = NN * HD / 4;
    if (i >= total4) return;
    int c = (i & 31) * 4;
    float4 v = ((float4*)X)[i];
    float4 r = ((const float4*)Res)[i];
    v.x = fmaxf(v.x * g_bnsc[1][c+0] + g_bnsh[1][c+0], 0.f) + fmaxf(r.x * g_bnsc[0][c+0] + g_bnsh[0][c+0], 0.f);
    v.y = fmaxf(v.y * g_bnsc[1][c+1] + g_bnsh[1][c+1], 0.f) + fmaxf(r.y * g_bnsc[0][c+1] + g_bnsh[0][c+1], 0.f);
    v.z = fmaxf(v.z * g_bnsc[1][c+2] + g_bnsh[1][c+2], 0.f) + fmaxf(r.z * g_bnsc[0][c+2] + g_bnsh[0][c+2], 0.f);
    v.w = fmaxf(v.w * g_bnsc[1][c+3] + g_bnsh[1][c+3], 0.f) + fmaxf(r.w * g_bnsc[0][c+3] + g_bnsh[0][c+3], 0.f);
    ((float4*)X)[i] = v;
}

// ---------------- head: h3 = relu(bn0(raw3)) + h2 ; MLP ----------------
__global__ void head_kernel(const float* __restrict__ W1,
                            const float* __restrict__ b1,
                            const float* __restrict__ W2,
                            const float* __restrict__ b2,
                            float* __restrict__ out) {
    const float* Raw = g_buf1;        // raw3
    const float* Res = g_buf0;        // h2
    __shared__ float W1s[HD * 64];
    __shared__ float W2s[64 * 2];
    __shared__ float b1s[64];
    __shared__ float scs[HD], shs[HD];
    for (int i = threadIdx.x; i < HD * 64; i += blockDim.x) W1s[i] = W1[i];
    if (threadIdx.x < 128) {
        W2s[threadIdx.x] = W2[threadIdx.x];
        scs[threadIdx.x] = g_bnsc[0][threadIdx.x];
        shs[threadIdx.x] = g_bnsh[0][threadIdx.x];
    }
    if (threadIdx.x < 64) b1s[threadIdx.x] = b1[threadIdx.x];
    __syncthreads();
    int lane = threadIdx.x & 31;
    int w = threadIdx.x >> 5;
    int wpg = gridDim.x * (blockDim.x >> 5);
    float b20 = b2[0], b21 = b2[1];
    int c0 = lane * 4;
    float sc0 = scs[c0], sc1 = scs[c0 + 1], sc2 = scs[c0 + 2], sc3 = scs[c0 + 3];
    float sh0 = shs[c0], sh1 = shs[c0 + 1], sh2 = shs[c0 + 2], sh3 = shs[c0 + 3];
    for (int n = blockIdx.x * (blockDim.x >> 5) + w; n < NN; n += wpg) {
        float4 h4 = __ldg((const float4*)(Raw + (size_t)n * HD) + lane);
        float4 r4 = __ldg((const float4*)(Res + (size_t)n * HD) + lane);
        float hv[4];
        hv[0] = fmaxf(h4.x * sc0 + sh0, 0.f) + r4.x;
        hv[1] = fmaxf(h4.y * sc1 + sh1, 0.f) + r4.y;
        hv[2] = fmaxf(h4.z * sc2 + sh2, 0.f) + r4.z;
        hv[3] = fmaxf(h4.w * sc3 + sh3, 0.f) + r4.w;
        float a0 = b1s[lane], a1 = b1s[lane + 32];
#pragma unroll
        for (int k = 0; k < HD; k++) {
            float v = __shfl_sync(0xffffffffu, hv[k & 3], k >> 2);
            a0 += v * W1s[k * 64 + lane];
            a1 += v * W1s[k * 64 + lane + 32];
        }
        a0 = fmaxf(a0, 0.f);
        a1 = fmaxf(a1, 0.f);
        float o0 = a0 * W2s[lane * 2 + 0] + a1 * W2s[(lane + 32) * 2 + 0];
        float o1 = a0 * W2s[lane * 2 + 1] + a1 * W2s[(lane + 32) * 2 + 1];
#pragma unroll
        for (int off = 16; off; off >>= 1) {
            o0 += __shfl_xor_sync(0xffffffffu, o0, off);
            o1 += __shfl_xor_sync(0xffffffffu, o1, off);
        }
        if (lane == 0) {
            out[n * 2 + 0] = o0 + b20;
            out[n * 2 + 1] = o1 + b21;
        }
    }
}

// ---------------- launch (kernel launches ONLY) ----------------
extern "C" void kernel_launch(void* const* d_in, const int* in_sizes, int n_in,
                              void* d_out, int out_size) {
    const float* features = (const float*)d_in[0];
    const void*  edge     = d_in[1];
    const float* emb_W    = (const float*)d_in[2];
    const float* emb_b    = (const float*)d_in[3];
    const float* Wself    = (const float*)d_in[4];
    const float* Wneigh   = (const float*)d_in[5];
    const float* conv_b   = (const float*)d_in[6];
    const float* gamma    = (const float*)d_in[7];
    const float* beta     = (const float*)d_in[8];
    const float* W1       = (const float*)d_in[9];
    const float* b1       = (const float*)d_in[10];
    const float* W2       = (const float*)d_in[11];
    const float* b2       = (const float*)d_in[12];
    float* out = (float*)d_out;

    detect_dtype_kernel<<<1, 128>>>(edge);
    extract_edges_kernel<<<(2 * EE + 255) / 256, 256>>>(edge);
    count_deg_kernel<<<(EE + 255) / 256, 256>>>();
    prep_weights_kernel<<<dim3(IND + 1, 4), 128>>>(emb_W, emb_b, Wself, Wneigh, conv_b);
    blocksum_kernel<<<NSCAN, SCB>>>();
    scan_bsum_kernel<<<1, 128>>>();
    fill_rowptr_kernel<<<NSCAN, SCB>>>();
    place_edges_kernel<<<(EE + 255) / 256, 256>>>();

    // ---- layer 1 in 12-dim space ----
    gather12_kernel<<<(NN * 4 + 255) / 256, 256>>>(features);   // msg12 -> buf0 alias
    gemm12_kernel<<<1024, 128>>>(features);                     // -> buf1 raw1 + stats
    bn_finalize_kernel<<<1, HD>>>(gamma, beta, 0);              // BN1 -> slot 0

    // ---- layer 2: fused gather+GEMM, reads buf1 (act BN1), -> buf0 raw2
    gemm_fused_kernel<<<(NN + BM - 1) / BM, 256>>>(
        1, 0, Wself + (size_t)1 * HD * HD, Wneigh + (size_t)1 * HD * HD,
        conv_b + 1 * HD);
    bn_finalize_kernel<<<1, HD>>>(gamma + 1 * HD, beta + 1 * HD, 1);  // BN2 -> slot 1
    bn_apply2_kernel<<<(NN * HD / 4 + 255) / 256, 256>>>();     // buf0 = h2

    // ---- layer 3: fused gather+GEMM, reads buf0 (h2), -> buf1 raw3 ----
    gemm_fused_kernel<<<(NN + BM - 1) / BM, 256>>>(
        0, -1, Wself + (size_t)2 * HD * HD, Wneigh + (size_t)2 * HD * HD,
        conv_b + 2 * HD);
    bn_finalize_kernel<<<1, HD>>>(gamma + 2 * HD, beta + 2 * HD, 0);  // BN3 -> slot 0
    head_kernel<<<1024, 256>>>(W1, b1, W2, b2, out);             // raw3(buf1), h2(buf0)
}

// round 14
// speedup vs baseline: 1.3863x; 1.3863x over previous
#include <cuda_runtime.h>
#include <mma.h>

using namespace nvcuda;

#define NN 100000
#define EE 600000
#define IND 12
#define HD  128
#define NL  3
#define BNEPS 1e-5f
#define SCB 1024
#define NSCAN ((NN + SCB - 1) / SCB)   // 98

// ---------------- device scratch (static, no allocation) ----------------
// GB300 fabric-init (802) flake rate grows with static size: keep minimal.
// src/dst alias into g_buf1 (dead until gemm12); cursor aliases into
// g_buf0 past the msg12 region (dead until gather12).
__device__ float g_buf0[NN * HD];
__device__ float g_buf1[NN * HD];
__device__ int   g_adj[EE];
__device__ int   g_rowptr[NN + 1];
__device__ int   g_deg[NN];
__device__ float g_invdeg[NN];
__device__ int   g_bsum[NSCAN];
__device__ float g_W1c[IND * HD];
__device__ float g_W2c[IND * HD];
__device__ float g_bias1[HD];
__device__ float g_biasd[HD];
__device__ float g_sum[HD];
__device__ float g_sqsum[HD];
__device__ float g_bnsc[2][HD];
__device__ float g_bnsh[2][HD];
__device__ int   g_is64;

__device__ __forceinline__ float* selbuf(int s) { return s ? g_buf1 : g_buf0; }
__device__ __forceinline__ int* srcp() { return (int*)g_buf1; }
__device__ __forceinline__ int* dstp() { return ((int*)g_buf1) + EE; }
__device__ __forceinline__ int* curp() { return (int*)(g_buf0 + (size_t)NN * IND); }

// ---------------- dtype detection ----------------
__global__ void detect_dtype_kernel(const void* p) {
    const int* pi = (const int*)p;
    int nz = 0;
    for (int k = threadIdx.x; k < 256; k += blockDim.x)
        nz |= (pi[2 * k + 1] != 0);
    nz = __syncthreads_or(nz);
    if (threadIdx.x == 0) g_is64 = nz ? 0 : 1;
}

// extract edges + zero deg + zero folded-weight accumulators
__global__ void extract_edges_kernel(const void* p) {
    int i = blockIdx.x * blockDim.x + threadIdx.x;
    if (i < NN) g_deg[i] = 0;
    if (i < IND * HD) { g_W1c[i] = 0.f; g_W2c[i] = 0.f; }
    if (i < HD) { g_bias1[i] = 0.f; g_biasd[i] = 0.f; }
    if (i >= 2 * EE) return;
    int v;
    if (g_is64) v = (int)((const long long*)p)[i];
    else        v = ((const int*)p)[i];
    if (i < EE) srcp()[i] = v;
    else        dstp()[i - EE] = v;
}

__global__ void count_deg_kernel() {
    int e = blockIdx.x * blockDim.x + threadIdx.x;
    if (e < EE) atomicAdd(&g_deg[dstp()[e]], 1);
}

// ---------------- layer-1 folded weights, parallel over K-chunks --------
__global__ void prep_weights_kernel(const float* __restrict__ embW,
                                    const float* __restrict__ emb_b,
                                    const float* __restrict__ Ws,
                                    const float* __restrict__ Wn,
                                    const float* __restrict__ cb) {
    int c = threadIdx.x;
    int k = blockIdx.x;             // 0..12 (12 = bias row)
    int j0 = blockIdx.y * 32;
    const float* v = (k < IND) ? (embW + k * HD) : emb_b;
    float a0 = 0.f, a1 = 0.f, a2 = 0.f, a3 = 0.f;
    float b0 = 0.f, b1v = 0.f, b2v = 0.f, b3 = 0.f;
#pragma unroll
    for (int j = j0; j < j0 + 32; j += 4) {
        float e0 = __ldg(&v[j + 0]), e1 = __ldg(&v[j + 1]);
        float e2 = __ldg(&v[j + 2]), e3 = __ldg(&v[j + 3]);
        a0 += e0 * __ldg(&Ws[(j + 0) * HD + c]);
        a1 += e1 * __ldg(&Ws[(j + 1) * HD + c]);
        a2 += e2 * __ldg(&Ws[(j + 2) * HD + c]);
        a3 += e3 * __ldg(&Ws[(j + 3) * HD + c]);
        b0  += e0 * __ldg(&Wn[(j + 0) * HD + c]);
        b1v += e1 * __ldg(&Wn[(j + 1) * HD + c]);
        b2v += e2 * __ldg(&Wn[(j + 2) * HD + c]);
        b3  += e3 * __ldg(&Wn[(j + 3) * HD + c]);
    }
    float ra = (a0 + a1) + (a2 + a3);
    float rb = (b0 + b1v) + (b2v + b3);
    if (k < IND) {
        atomicAdd(&g_W1c[k * HD + c], ra);
        atomicAdd(&g_W2c[k * HD + c], rb);
    } else {
        atomicAdd(&g_bias1[c], ra + (blockIdx.y == 0 ? __ldg(&cb[c]) : 0.f));
        atomicAdd(&g_biasd[c], rb);
    }
}

// ---------------- parallel CSR scan -------------------------------------
__global__ void blocksum_kernel() {          // <<<NSCAN, SCB>>>
    __shared__ int wsum[32];
    int i = blockIdx.x * SCB + threadIdx.x;
    int v = (i < NN) ? g_deg[i] : 0;
    int lane = threadIdx.x & 31, wid = threadIdx.x >> 5;
#pragma unroll
    for (int off = 16; off; off >>= 1) v += __shfl_down_sync(0xffffffffu, v, off);
    if (lane == 0) wsum[wid] = v;
    __syncthreads();
    if (wid == 0) {
        int t = (lane < 32) ? wsum[lane] : 0;
#pragma unroll
        for (int off = 16; off; off >>= 1) t += __shfl_down_sync(0xffffffffu, t, off);
        if (lane == 0) g_bsum[blockIdx.x] = t;
    }
}
__global__ void scan_bsum_kernel() {         // <<<1, 128>>>  (+BN sum init)
    __shared__ int vals[NSCAN];
    int tid = threadIdx.x;
    if (tid < HD) { g_sum[tid] = 0.f; g_sqsum[tid] = 0.f; }
    if (tid < NSCAN) vals[tid] = g_bsum[tid];
    __syncthreads();
    if (tid == 0) {
        int acc = 0;
        for (int k = 0; k < NSCAN; k++) { int t = vals[k]; vals[k] = acc; acc += t; }
        g_rowptr[NN] = acc;
    }
    __syncthreads();
    if (tid < NSCAN) g_bsum[tid] = vals[tid];
}
__global__ void fill_rowptr_kernel() {       // <<<NSCAN, SCB>>>  (+invdeg)
    __shared__ int wsum[32];
    int i = blockIdx.x * SCB + threadIdx.x;
    int lane = threadIdx.x & 31, wid = threadIdx.x >> 5;
    int v = (i < NN) ? g_deg[i] : 0;
    int inc = v;
#pragma unroll
    for (int off = 1; off < 32; off <<= 1) {
        int t = __shfl_up_sync(0xffffffffu, inc, off);
        if (lane >= off) inc += t;
    }
    if (lane == 31) wsum[wid] = inc;
    __syncthreads();
    if (wid == 0) {
        int wi = wsum[lane];
#pragma unroll
        for (int off = 1; off < 32; off <<= 1) {
            int t = __shfl_up_sync(0xffffffffu, wi, off);
            if (lane >= off) wi += t;
        }
        wsum[lane] = wi;
    }
    __syncthreads();
    int excl = inc - v + (wid ? wsum[wid - 1] : 0) + g_bsum[blockIdx.x];
    if (i < NN) {
        curp()[i] = excl;
        g_rowptr[i] = excl;
        g_invdeg[i] = 1.f / fmaxf((float)v, 1.f);
    }
}

__global__ void place_edges_kernel() {
    int e = blockIdx.x * blockDim.x + threadIdx.x;
    if (e >= EE) return;
    int d = dstp()[e];
    int pos = atomicAdd(&curp()[d], 1);
    g_adj[pos] = srcp()[e];
}

// ---------------- layer-1 gather in 12-dim feature space ---------------
__global__ void gather12_kernel(const float* __restrict__ F) {
    float* __restrict__ msg12 = g_buf0;   // alias
    int gid = blockIdx.x * blockDim.x + threadIdx.x;
    int node = gid >> 2, ch = gid & 3;
    if (node >= NN || ch >= 3) return;
    int beg = __ldg(&g_rowptr[node]);
    int end = __ldg(&g_rowptr[node + 1]);
    float4 acc = make_float4(0.f, 0.f, 0.f, 0.f);
    for (int j = beg; j < end; j++) {
        int s = __ldg(&g_adj[j]);
        float4 v = __ldg((const float4*)(F + (size_t)s * IND) + ch);
        acc.x += v.x; acc.y += v.y; acc.z += v.z; acc.w += v.w;
    }
    float sc = g_invdeg[node];
    acc.x *= sc; acc.y *= sc; acc.z *= sc; acc.w *= sc;
    *(float4*)(msg12 + (size_t)node * IND + ch * 4) = acc;
}

// ---------------- layer-1 GEMM (K=12, fp32 FFMA) -> buf1 raw1 ----------
#define G12NB 8
__global__ void __launch_bounds__(128)
gemm12_kernel(const float* __restrict__ F) {
    const float* __restrict__ msg12 = g_buf0;  // alias
    __shared__ float W1s[IND * HD], W2s[IND * HD];
    __shared__ float Fs[G12NB][IND], Ms[G12NB][IND];
    int c = threadIdx.x;
    for (int i = c; i < IND * HD; i += 128) { W1s[i] = g_W1c[i]; W2s[i] = g_W2c[i]; }
    float bfx = g_bias1[c], bdg = g_biasd[c];
    int nrow_off = c / IND, kk = c % IND;
    float s = 0.f, s2 = 0.f;
    float* C = g_buf1;
    for (int base = blockIdx.x * G12NB; base < NN; base += gridDim.x * G12NB) {
        __syncthreads();
        if (c < 8 * IND) {
            int n = base + nrow_off;
            Fs[nrow_off][kk] = (n < NN) ? __ldg(&F[(size_t)n * IND + kk]) : 0.f;
            Ms[nrow_off][kk] = (n < NN) ? msg12[(size_t)n * IND + kk] : 0.f;
        }
        __syncthreads();
#pragma unroll
        for (int r = 0; r < G12NB; r++) {
            int n = base + r;
            if (n >= NN) break;
            float acc = bfx + (__ldg(&g_deg[n]) ? bdg : 0.f);
#pragma unroll
            for (int k = 0; k < IND; k++)
                acc += Fs[r][k] * W1s[k * HD + c] + Ms[r][k] * W2s[k * HD + c];
            C[(size_t)n * HD + c] = acc;
            s += acc; s2 += acc * acc;
        }
    }
    atomicAdd(&g_sum[c], s);
    atomicAdd(&g_sqsum[c], s2);
}

// ---------------- CSR gather, plain, 4-neighbor unroll ------------------
__global__ void gather_kernel(int hsel) {
    const float* __restrict__ h = selbuf(hsel);
    float* __restrict__ msg = selbuf(hsel ^ 1);
    int gid = blockIdx.x * blockDim.x + threadIdx.x;
    int node = gid >> 5;
    if (node >= NN) return;
    int lane = gid & 31;
    int beg = __ldg(&g_rowptr[node]);
    int end = __ldg(&g_rowptr[node + 1]);
    float4 acc = make_float4(0.f, 0.f, 0.f, 0.f);
    int j = beg;
    for (; j + 3 < end; j += 4) {
        int s0 = __ldg(&g_adj[j]);
        int s1 = __ldg(&g_adj[j + 1]);
        int s2 = __ldg(&g_adj[j + 2]);
        int s3 = __ldg(&g_adj[j + 3]);
        float4 a = __ldg((const float4*)(h + (size_t)s0 * HD) + lane);
        float4 b = __ldg((const float4*)(h + (size_t)s1 * HD) + lane);
        float4 c = __ldg((const float4*)(h + (size_t)s2 * HD) + lane);
        float4 d = __ldg((const float4*)(h + (size_t)s3 * HD) + lane);
        acc.x += (a.x + b.x) + (c.x + d.x);
        acc.y += (a.y + b.y) + (c.y + d.y);
        acc.z += (a.z + b.z) + (c.z + d.z);
        acc.w += (a.w + b.w) + (c.w + d.w);
    }
    for (; j < end; j++) {
        int s0 = __ldg(&g_adj[j]);
        float4 a = __ldg((const float4*)(h + (size_t)s0 * HD) + lane);
        acc.x += a.x; acc.y += a.y; acc.z += a.z; acc.w += a.w;
    }
    float sc = g_invdeg[node];
    acc.x *= sc; acc.y *= sc; acc.z *= sc; acc.w *= sc;
    ((float4*)(msg + (size_t)node * HD))[lane] = acc;
}

// ---------------- CSR gather with on-the-fly BN+ReLU, 4-unroll ----------
__global__ void gather_bn_kernel(int hsel, int slot) {
    const float* __restrict__ raw = selbuf(hsel);
    float* __restrict__ msg = selbuf(hsel ^ 1);
    int gid = blockIdx.x * blockDim.x + threadIdx.x;
    int node = gid >> 5;
    if (node >= NN) return;
    int lane = gid & 31;
    int c0 = lane * 4;
    float s0c = g_bnsc[slot][c0 + 0], s1c = g_bnsc[slot][c0 + 1];
    float s2c = g_bnsc[slot][c0 + 2], s3c = g_bnsc[slot][c0 + 3];
    float h0c = g_bnsh[slot][c0 + 0], h1c = g_bnsh[slot][c0 + 1];
    float h2c = g_bnsh[slot][c0 + 2], h3c = g_bnsh[slot][c0 + 3];
    int beg = __ldg(&g_rowptr[node]);
    int end = __ldg(&g_rowptr[node + 1]);
    float4 acc = make_float4(0.f, 0.f, 0.f, 0.f);
    int j = beg;
    for (; j + 3 < end; j += 4) {
        int s0 = __ldg(&g_adj[j]);
        int s1 = __ldg(&g_adj[j + 1]);
        int s2 = __ldg(&g_adj[j + 2]);
        int s3 = __ldg(&g_adj[j + 3]);
        float4 a = __ldg((const float4*)(raw + (size_t)s0 * HD) + lane);
        float4 b = __ldg((const float4*)(raw + (size_t)s1 * HD) + lane);
        float4 c = __ldg((const float4*)(raw + (size_t)s2 * HD) + lane);
        float4 d = __ldg((const float4*)(raw + (size_t)s3 * HD) + lane);
        acc.x += fmaxf(a.x * s0c + h0c, 0.f) + fmaxf(b.x * s0c + h0c, 0.f)
               + fmaxf(c.x * s0c + h0c, 0.f) + fmaxf(d.x * s0c + h0c, 0.f);
        acc.y += fmaxf(a.y * s1c + h1c, 0.f) + fmaxf(b.y * s1c + h1c, 0.f)
               + fmaxf(c.y * s1c + h1c, 0.f) + fmaxf(d.y * s1c + h1c, 0.f);
        acc.z += fmaxf(a.z * s2c + h2c, 0.f) + fmaxf(b.z * s2c + h2c, 0.f)
               + fmaxf(c.z * s2c + h2c, 0.f) + fmaxf(d.z * s2c + h2c, 0.f);
        acc.w += fmaxf(a.w * s3c + h3c, 0.f) + fmaxf(b.w * s3c + h3c, 0.f)
               + fmaxf(c.w * s3c + h3c, 0.f) + fmaxf(d.w * s3c + h3c, 0.f);
    }
    for (; j < end; j++) {
        int s = __ldg(&g_adj[j]);
        float4 a = __ldg((const float4*)(raw + (size_t)s * HD) + lane);
        acc.x += fmaxf(a.x * s0c + h0c, 0.f);
        acc.y += fmaxf(a.y * s1c + h1c, 0.f);
        acc.z += fmaxf(a.z * s2c + h2c, 0.f);
        acc.w += fmaxf(a.w * s3c + h3c, 0.f);
    }
    float sc = g_invdeg[node];
    acc.x *= sc; acc.y *= sc; acc.z *= sc; acc.w *= sc;
    ((float4*)(msg + (size_t)node * HD))[lane] = acc;
}

// ---------------- fused dual GEMM (tf32, BK=16, prefetched tiles) -------
#define BM 128
#define BK 16
#define ALD (BK + 4)
#define BLD (HD + 4)
#define WTLD 20
__global__ void __launch_bounds__(256)
gemm_layer_kernel(int hsel, int bnslot,
                  const float* __restrict__ Wsp,
                  const float* __restrict__ Wnp,
                  const float* __restrict__ bias) {
    __shared__ float As[BM * ALD];
    __shared__ float Bs[BK * BLD];
    __shared__ float wtile[8][16 * WTLD];
    __shared__ float colsum[HD], colsq[HD];
    __shared__ float bsc[HD], bsh[HD];

    const float* A1 = selbuf(hsel);
    float* Msg = selbuf(hsel ^ 1);
    float* C = Msg;  // in-place
    const int nrows = NN;
    int tid = threadIdx.x;
    int w = tid >> 5, lane = tid & 31;
    int wm = w & 3, wn = w >> 2;
    int row0 = blockIdx.x * BM;

    if (tid < HD) {
        colsum[tid] = 0.f; colsq[tid] = 0.f;
        if (bnslot >= 0) { bsc[tid] = g_bnsc[bnslot][tid]; bsh[tid] = g_bnsh[bnslot][tid]; }
    }

    // A-tile thread mapping (2 float4 per thread)
    int am0 = (tid * 2) >> 2,     ak0 = ((tid * 2) & 3) * 4;
    int am1 = (tid * 2 + 1) >> 2, ak1 = ((tid * 2 + 1) & 3) * 4;
    int arc0 = (row0 + am0) < nrows ? (row0 + am0) : nrows - 1;
    int arc1 = (row0 + am1) < nrows ? (row0 + am1) : nrows - 1;
    // W-tile thread mapping
    int wk0 = (tid * 2) >> 5,     wc0 = ((tid * 2) & 31) * 4;
    int wk1 = (tid * 2 + 1) >> 5, wc1 = ((tid * 2 + 1) & 31) * 4;

    wmma::fragment<wmma::accumulator, 16, 16, 8, float> acc[2][4];
#pragma unroll
    for (int i = 0; i < 2; i++)
#pragma unroll
        for (int j = 0; j < 4; j++) wmma::fill_fragment(acc[i][j], 0.f);

    for (int pass = 0; pass < 2; ++pass) {
        const float* A = pass ? Msg : A1;
        const float* W = pass ? Wnp : Wsp;
        int abn = (pass == 0 && bnslot >= 0);
        for (int k0 = 0; k0 < HD; k0 += BK) {
            // ---- prefetch tiles to registers BEFORE the barrier (latency
            // overlaps previous iteration's MMA + the barrier itself) ----
            float4 va0 = __ldg((const float4*)(A + (size_t)arc0 * HD + k0 + ak0));
            float4 va1 = __ldg((const float4*)(A + (size_t)arc1 * HD + k0 + ak1));
            float4 vw0 = __ldg((const float4*)(W + (size_t)(k0 + wk0) * HD + wc0));
            float4 vw1 = __ldg((const float4*)(W + (size_t)(k0 + wk1) * HD + wc1));
            __syncthreads();   // prior MMA done reading smem
            if (abn) {
                va0.x = fmaxf(va0.x * bsc[k0 + ak0 + 0] + bsh[k0 + ak0 + 0], 0.f);
                va0.y = fmaxf(va0.y * bsc[k0 + ak0 + 1] + bsh[k0 + ak0 + 1], 0.f);
                va0.z = fmaxf(va0.z * bsc[k0 + ak0 + 2] + bsh[k0 + ak0 + 2], 0.f);
                va0.w = fmaxf(va0.w * bsc[k0 + ak0 + 3] + bsh[k0 + ak0 + 3], 0.f);
                va1.x = fmaxf(va1.x * bsc[k0 + ak1 + 0] + bsh[k0 + ak1 + 0], 0.f);
                va1.y = fmaxf(va1.y * bsc[k0 + ak1 + 1] + bsh[k0 + ak1 + 1], 0.f);
                va1.z = fmaxf(va1.z * bsc[k0 + ak1 + 2] + bsh[k0 + ak1 + 2], 0.f);
                va1.w = fmaxf(va1.w * bsc[k0 + ak1 + 3] + bsh[k0 + ak1 + 3], 0.f);
            }
            As[am0 * ALD + ak0 + 0] = wmma::__float_to_tf32(va0.x);
            As[am0 * ALD + ak0 + 1] = wmma::__float_to_tf32(va0.y);
            As[am0 * ALD + ak0 + 2] = wmma::__float_to_tf32(va0.z);
            As[am0 * ALD + ak0 + 3] = wmma::__float_to_tf32(va0.w);
            As[am1 * ALD + ak1 + 0] = wmma::__float_to_tf32(va1.x);
            As[am1 * ALD + ak1 + 1] = wmma::__float_to_tf32(va1.y);
            As[am1 * ALD + ak1 + 2] = wmma::__float_to_tf32(va1.z);
            As[am1 * ALD + ak1 + 3] = wmma::__float_to_tf32(va1.w);
            Bs[wk0 * BLD + wc0 + 0] = wmma::__float_to_tf32(vw0.x);
            Bs[wk0 * BLD + wc0 + 1] = wmma::__float_to_tf32(vw0.y);
            Bs[wk0 * BLD + wc0 + 2] = wmma::__float_to_tf32(vw0.z);
            Bs[wk0 * BLD + wc0 + 3] = wmma::__float_to_tf32(vw0.w);
            Bs[wk1 * BLD + wc1 + 0] = wmma::__float_to_tf32(vw1.x);
            Bs[wk1 * BLD + wc1 + 1] = wmma::__float_to_tf32(vw1.y);
            Bs[wk1 * BLD + wc1 + 2] = wmma::__float_to_tf32(vw1.z);
            Bs[wk1 * BLD + wc1 + 3] = wmma::__float_to_tf32(vw1.w);
            __syncthreads();
#pragma unroll
            for (int ks = 0; ks < BK; ks += 8) {
                wmma::fragment<wmma::matrix_a, 16, 16, 8, wmma::precision::tf32, wmma::row_major> af[2];
                wmma::fragment<wmma::matrix_b, 16, 16, 8, wmma::precision::tf32, wmma::row_major> bf[4];
#pragma unroll
                for (int i = 0; i < 2; i++)
                    wmma::load_matrix_sync(af[i], &As[(wm * 32 + i * 16) * ALD + ks], ALD);
#pragma unroll
                for (int j = 0; j < 4; j++)
                    wmma::load_matrix_sync(bf[j], &Bs[ks * BLD + wn * 64 + j * 16], BLD);
#pragma unroll
                for (int i = 0; i < 2; i++)
#pragma unroll
                    for (int j = 0; j < 4; j++)
                        wmma::mma_sync(acc[i][j], af[i], bf[j], acc[i][j]);
            }
        }
    }

    float* wt = wtile[w];
    int cl = lane & 15;
    int rh = lane >> 4;
#pragma unroll
    for (int i = 0; i < 2; i++) {
#pragma unroll
        for (int j = 0; j < 4; j++) {
            wmma::store_matrix_sync(wt, acc[i][j], WTLD, wmma::mem_row_major);
            __syncwarp();
            int gc = wn * 64 + j * 16 + cl;
            int rbase = row0 + wm * 32 + i * 16 + rh * 8;
            float bia = bias[gc];
            float s = 0.f, s2 = 0.f;
#pragma unroll
            for (int r = 0; r < 8; r++) {
                int gr = rbase + r;
                float v = wt[(rh * 8 + r) * WTLD + cl] + bia;
                if (gr < nrows) {
                    C[(size_t)gr * HD + gc] = v;
                    s += v;
                    s2 += v * v;
                }
            }
            s  += __shfl_down_sync(0xffffffffu, s, 16);
            s2 += __shfl_down_sync(0xffffffffu, s2, 16);
            if (lane < 16) {
                atomicAdd(&colsum[gc], s);
                atomicAdd(&colsq[gc], s2);
            }
            __syncwarp();
        }
    }
    __syncthreads();
    if (tid < HD) {
        atomicAdd(&g_sum[tid], colsum[tid]);
        atomicAdd(&g_sqsum[tid], colsq[tid]);
    }
}

// ---------------- BN finalize into slot (+self-reset) ------------------
__global__ void bn_finalize_kernel(const float* __restrict__ gamma,
                                   const float* __restrict__ beta, int slot) {
    int c = threadIdx.x;
    float mu = g_sum[c] * (1.0f / NN);
    float var = g_sqsum[c] * (1.0f / NN) - mu * mu;
    float r = rsqrtf(var + BNEPS);
    float a = gamma[c] * r;
    g_bnsc[slot][c] = a;
    g_bnsh[slot][c] = beta[c] - mu * a;
    g_sum[c] = 0.f;
    g_sqsum[c] = 0.f;
}

// ---------------- layer-2 act: h2 = relu(bn1(raw2)) + relu(bn0(raw1)) --
__global__ void bn_apply2_kernel() {
    float* X = g_buf0;                // raw2 -> h2 (in place)
    const float* Res = g_buf1;        // raw1
    int i = blockIdx.x * blockDim.x + threadIdx.x;
    int total4 = NN * HD / 4;
    if (i >= total4) return;
    int c = (i & 31) * 4;
    float4 v = ((float4*)X)[i];
    float4 r = ((const float4*)Res)[i];
    v.x = fmaxf(v.x * g_bnsc[1][c+0] + g_bnsh[1][c+0], 0.f) + fmaxf(r.x * g_bnsc[0][c+0] + g_bnsh[0][c+0], 0.f);
    v.y = fmaxf(v.y * g_bnsc[1][c+1] + g_bnsh[1][c+1], 0.f) + fmaxf(r.y * g_bnsc[0][c+1] + g_bnsh[0][c+1], 0.f);
    v.z = fmaxf(v.z * g_bnsc[1][c+2] + g_bnsh[1][c+2], 0.f) + fmaxf(r.z * g_bnsc[0][c+2] + g_bnsh[0][c+2], 0.f);
    v.w = fmaxf(v.w * g_bnsc[1][c+3] + g_bnsh[1][c+3], 0.f) + fmaxf(r.w * g_bnsc[0][c+3] + g_bnsh[0][c+3], 0.f);
    ((float4*)X)[i] = v;
}

// ---------------- head: h3 = relu(bn0(raw3)) + h2 ; MLP ----------------
__global__ void head_kernel(const float* __restrict__ W1,
                            const float* __restrict__ b1,
                            const float* __restrict__ W2,
                            const float* __restrict__ b2,
                            float* __restrict__ out) {
    const float* Raw = g_buf1;        // raw3
    const float* Res = g_buf0;        // h2
    __shared__ float W1s[HD * 64];
    __shared__ float W2s[64 * 2];
    __shared__ float b1s[64];
    __shared__ float scs[HD], shs[HD];
    for (int i = threadIdx.x; i < HD * 64; i += blockDim.x) W1s[i] = W1[i];
    if (threadIdx.x < 128) {
        W2s[threadIdx.x] = W2[threadIdx.x];
        scs[threadIdx.x] = g_bnsc[0][threadIdx.x];
        shs[threadIdx.x] = g_bnsh[0][threadIdx.x];
    }
    if (threadIdx.x < 64) b1s[threadIdx.x] = b1[threadIdx.x];
    __syncthreads();
    int lane = threadIdx.x & 31;
    int w = threadIdx.x >> 5;
    int wpg = gridDim.x * (blockDim.x >> 5);
    float b20 = b2[0], b21 = b2[1];
    int c0 = lane * 4;
    float sc0 = scs[c0], sc1 = scs[c0 + 1], sc2 = scs[c0 + 2], sc3 = scs[c0 + 3];
    float sh0 = shs[c0], sh1 = shs[c0 + 1], sh2 = shs[c0 + 2], sh3 = shs[c0 + 3];
    for (int n = blockIdx.x * (blockDim.x >> 5) + w; n < NN; n += wpg) {
        float4 h4 = __ldg((const float4*)(Raw + (size_t)n * HD) + lane);
        float4 r4 = __ldg((const float4*)(Res + (size_t)n * HD) + lane);
        float hv[4];
        hv[0] = fmaxf(h4.x * sc0 + sh0, 0.f) + r4.x;
        hv[1] = fmaxf(h4.y * sc1 + sh1, 0.f) + r4.y;
        hv[2] = fmaxf(h4.z * sc2 + sh2, 0.f) + r4.z;
        hv[3] = fmaxf(h4.w * sc3 + sh3, 0.f) + r4.w;
        float a0 = b1s[lane], a1 = b1s[lane + 32];
#pragma unroll
        for (int k = 0; k < HD; k++) {
            float v = __shfl_sync(0xffffffffu, hv[k & 3], k >> 2);
            a0 += v * W1s[k * 64 + lane];
            a1 += v * W1s[k * 64 + lane + 32];
        }
        a0 = fmaxf(a0, 0.f);
        a1 = fmaxf(a1, 0.f);
        float o0 = a0 * W2s[lane * 2 + 0] + a1 * W2s[(lane + 32) * 2 + 0];
        float o1 = a0 * W2s[lane * 2 + 1] + a1 * W2s[(lane + 32) * 2 + 1];
#pragma unroll
        for (int off = 16; off; off >>= 1) {
            o0 += __shfl_xor_sync(0xffffffffu, o0, off);
            o1 += __shfl_xor_sync(0xffffffffu, o1, off);
        }
        if (lane == 0) {
            out[n * 2 + 0] = o0 + b20;
            out[n * 2 + 1] = o1 + b21;
        }
    }
}

// ---------------- launch (kernel launches ONLY) ----------------
extern "C" void kernel_launch(void* const* d_in, const int* in_sizes, int n_in,
                              void* d_out, int out_size) {
    const float* features = (const float*)d_in[0];
    const void*  edge     = d_in[1];
    const float* emb_W    = (const float*)d_in[2];
    const float* emb_b    = (const float*)d_in[3];
    const float* Wself    = (const float*)d_in[4];
    const float* Wneigh   = (const float*)d_in[5];
    const float* conv_b   = (const float*)d_in[6];
    const float* gamma    = (const float*)d_in[7];
    const float* beta     = (const float*)d_in[8];
    const float* W1       = (const float*)d_in[9];
    const float* b1       = (const float*)d_in[10];
    const float* W2       = (const float*)d_in[11];
    const float* b2       = (const float*)d_in[12];
    float* out = (float*)d_out;

    detect_dtype_kernel<<<1, 128>>>(edge);
    extract_edges_kernel<<<(2 * EE + 255) / 256, 256>>>(edge);
    count_deg_kernel<<<(EE + 255) / 256, 256>>>();
    prep_weights_kernel<<<dim3(IND + 1, 4), 128>>>(emb_W, emb_b, Wself, Wneigh, conv_b);
    blocksum_kernel<<<NSCAN, SCB>>>();
    scan_bsum_kernel<<<1, 128>>>();
    fill_rowptr_kernel<<<NSCAN, SCB>>>();
    place_edges_kernel<<<(EE + 255) / 256, 256>>>();

    // ---- layer 1 in 12-dim space ----
    gather12_kernel<<<(NN * 4 + 255) / 256, 256>>>(features);   // msg12 -> buf0 alias
    gemm12_kernel<<<1024, 128>>>(features);                     // -> buf1 raw1 + stats
    bn_finalize_kernel<<<1, HD>>>(gamma, beta, 0);              // BN1 -> slot 0

    // ---- layer 2 (h1 never materialized; BN1 applied on the fly) ----
    gather_bn_kernel<<<(NN * 32 + 255) / 256, 256>>>(1, 0);     // raw1(buf1) -> msg(buf0)
    gemm_layer_kernel<<<(NN + BM - 1) / BM, 256>>>(
        1, 0, Wself + (size_t)1 * HD * HD, Wneigh + (size_t)1 * HD * HD,
        conv_b + 1 * HD);                                        // -> buf0 raw2
    bn_finalize_kernel<<<1, HD>>>(gamma + 1 * HD, beta + 1 * HD, 1);  // BN2 -> slot 1
    bn_apply2_kernel<<<(NN * HD / 4 + 255) / 256, 256>>>();     // buf0 = h2

    // ---- layer 3 ----
    gather_kernel<<<(NN * 32 + 255) / 256, 256>>>(0);           // h2(buf0) -> msg(buf1)
    gemm_layer_kernel<<<(NN + BM - 1) / BM, 256>>>(
        0, -1, Wself + (size_t)2 * HD * HD, Wneigh + (size_t)2 * HD * HD,
        conv_b + 2 * HD);                                        // -> buf1 raw3
    bn_finalize_kernel<<<1, HD>>>(gamma + 2 * HD, beta + 2 * HD, 0);  // BN3 -> slot 0
    head_kernel<<<1024, 256>>>(W1, b1, W2, b2, out);             // raw3(buf1), h2(buf0)
}

// round 15
// speedup vs baseline: 1.6967x; 1.2239x over previous
#include <cuda_runtime.h>
#include <mma.h>

using namespace nvcuda;

#define NN 100000
#define EE 600000
#define IND 12
#define HD  128
#define NL  3
#define BNEPS 1e-5f
#define SCB 1024
#define NSCAN ((NN + SCB - 1) / SCB)   // 98

// ---------------- device scratch (static, no allocation) ----------------
// GB300 fabric-init (802) flake rate grows with static size: keep minimal.
// src/dst alias into g_buf1 (dead until gemm12); cursor aliases into
// g_buf0 past the msg12 region (dead until gather12).
__device__ float g_buf0[NN * HD];
__device__ float g_buf1[NN * HD];
__device__ int   g_adj[EE];
__device__ int   g_rowptr[NN + 1];
__device__ int   g_deg[NN];
__device__ float g_invdeg[NN];
__device__ int   g_bsum[NSCAN];
__device__ float g_W1c[IND * HD];
__device__ float g_W2c[IND * HD];
__device__ float g_bias1[HD];
__device__ float g_biasd[HD];
__device__ float g_sum[HD];
__device__ float g_sqsum[HD];
__device__ float g_bnsc[2][HD];
__device__ float g_bnsh[2][HD];

__device__ __forceinline__ float* selbuf(int s) { return s ? g_buf1 : g_buf0; }
__device__ __forceinline__ int* srcp() { return (int*)g_buf1; }
__device__ __forceinline__ int* dstp() { return ((int*)g_buf1) + EE; }
__device__ __forceinline__ int* curp() { return (int*)(g_buf0 + (size_t)NN * IND); }

// ---------------- zero pass (deg + folded-weight accumulators) ----------
__global__ void zero_kernel() {
    int i = blockIdx.x * blockDim.x + threadIdx.x;
    if (i < NN) g_deg[i] = 0;
    if (i < IND * HD) { g_W1c[i] = 0.f; g_W2c[i] = 0.f; }
    if (i < HD) { g_bias1[i] = 0.f; g_biasd[i] = 0.f; }
}

// extract edges + inline degree count (per-block dtype detection)
__global__ void extract_count_kernel(const void* p) {
    const int* pi = (const int*)p;
    int nz = (threadIdx.x < 256) ? (pi[2 * threadIdx.x + 1] != 0) : 0;
    nz = __syncthreads_or(nz);      // nz==0 -> int64 layout
    int i = blockIdx.x * blockDim.x + threadIdx.x;
    if (i >= 2 * EE) return;
    int v;
    if (!nz) v = (int)((const long long*)p)[i];
    else     v = pi[i];
    if (i < EE) {
        srcp()[i] = v;
    } else {
        dstp()[i - EE] = v;
        atomicAdd(&g_deg[v], 1);
    }
}

// ---------------- layer-1 folded weights, parallel over K-chunks --------
__global__ void prep_weights_kernel(const float* __restrict__ embW,
                                    const float* __restrict__ emb_b,
                                    const float* __restrict__ Ws,
                                    const float* __restrict__ Wn,
                                    const float* __restrict__ cb) {
    int c = threadIdx.x;
    int k = blockIdx.x;             // 0..12 (12 = bias row)
    int j0 = blockIdx.y * 32;
    const float* v = (k < IND) ? (embW + k * HD) : emb_b;
    float a0 = 0.f, a1 = 0.f, a2 = 0.f, a3 = 0.f;
    float b0 = 0.f, b1v = 0.f, b2v = 0.f, b3 = 0.f;
#pragma unroll
    for (int j = j0; j < j0 + 32; j += 4) {
        float e0 = __ldg(&v[j + 0]), e1 = __ldg(&v[j + 1]);
        float e2 = __ldg(&v[j + 2]), e3 = __ldg(&v[j + 3]);
        a0 += e0 * __ldg(&Ws[(j + 0) * HD + c]);
        a1 += e1 * __ldg(&Ws[(j + 1) * HD + c]);
        a2 += e2 * __ldg(&Ws[(j + 2) * HD + c]);
        a3 += e3 * __ldg(&Ws[(j + 3) * HD + c]);
        b0  += e0 * __ldg(&Wn[(j + 0) * HD + c]);
        b1v += e1 * __ldg(&Wn[(j + 1) * HD + c]);
        b2v += e2 * __ldg(&Wn[(j + 2) * HD + c]);
        b3  += e3 * __ldg(&Wn[(j + 3) * HD + c]);
    }
    float ra = (a0 + a1) + (a2 + a3);
    float rb = (b0 + b1v) + (b2v + b3);
    if (k < IND) {
        atomicAdd(&g_W1c[k * HD + c], ra);
        atomicAdd(&g_W2c[k * HD + c], rb);
    } else {
        atomicAdd(&g_bias1[c], ra + (blockIdx.y == 0 ? __ldg(&cb[c]) : 0.f));
        atomicAdd(&g_biasd[c], rb);
    }
}

// ---------------- parallel CSR scan -------------------------------------
__global__ void blocksum_kernel() {          // <<<NSCAN, SCB>>>
    __shared__ int wsum[32];
    int i = blockIdx.x * SCB + threadIdx.x;
    int v = (i < NN) ? g_deg[i] : 0;
    int lane = threadIdx.x & 31, wid = threadIdx.x >> 5;
#pragma unroll
    for (int off = 16; off; off >>= 1) v += __shfl_down_sync(0xffffffffu, v, off);
    if (lane == 0) wsum[wid] = v;
    __syncthreads();
    if (wid == 0) {
        int t = (lane < 32) ? wsum[lane] : 0;
#pragma unroll
        for (int off = 16; off; off >>= 1) t += __shfl_down_sync(0xffffffffu, t, off);
        if (lane == 0) g_bsum[blockIdx.x] = t;
    }
}
__global__ void scan_bsum_kernel() {         // <<<1, 128>>>  (+BN sum init)
    __shared__ int vals[NSCAN];
    int tid = threadIdx.x;
    if (tid < HD) { g_sum[tid] = 0.f; g_sqsum[tid] = 0.f; }
    if (tid < NSCAN) vals[tid] = g_bsum[tid];
    __syncthreads();
    if (tid == 0) {
        int acc = 0;
        for (int k = 0; k < NSCAN; k++) { int t = vals[k]; vals[k] = acc; acc += t; }
        g_rowptr[NN] = acc;
    }
    __syncthreads();
    if (tid < NSCAN) g_bsum[tid] = vals[tid];
}
__global__ void fill_rowptr_kernel() {       // <<<NSCAN, SCB>>>  (+invdeg)
    __shared__ int wsum[32];
    int i = blockIdx.x * SCB + threadIdx.x;
    int lane = threadIdx.x & 31, wid = threadIdx.x >> 5;
    int v = (i < NN) ? g_deg[i] : 0;
    int inc = v;
#pragma unroll
    for (int off = 1; off < 32; off <<= 1) {
        int t = __shfl_up_sync(0xffffffffu, inc, off);
        if (lane >= off) inc += t;
    }
    if (lane == 31) wsum[wid] = inc;
    __syncthreads();
    if (wid == 0) {
        int wi = wsum[lane];
#pragma unroll
        for (int off = 1; off < 32; off <<= 1) {
            int t = __shfl_up_sync(0xffffffffu, wi, off);
            if (lane >= off) wi += t;
        }
        wsum[lane] = wi;
    }
    __syncthreads();
    int excl = inc - v + (wid ? wsum[wid - 1] : 0) + g_bsum[blockIdx.x];
    if (i < NN) {
        curp()[i] = excl;
        g_rowptr[i] = excl;
        g_invdeg[i] = 1.f / fmaxf((float)v, 1.f);
    }
}

__global__ void place_edges_kernel() {
    int e = blockIdx.x * blockDim.x + threadIdx.x;
    if (e >= EE) return;
    int d = dstp()[e];
    int pos = atomicAdd(&curp()[d], 1);
    g_adj[pos] = srcp()[e];
}

// ---------------- layer-1 gather in 12-dim feature space ---------------
__global__ void gather12_kernel(const float* __restrict__ F) {
    float* __restrict__ msg12 = g_buf0;   // alias
    int gid = blockIdx.x * blockDim.x + threadIdx.x;
    int node = gid >> 2, ch = gid & 3;
    if (node >= NN || ch >= 3) return;
    int beg = __ldg(&g_rowptr[node]);
    int end = __ldg(&g_rowptr[node + 1]);
    float4 acc = make_float4(0.f, 0.f, 0.f, 0.f);
    for (int j = beg; j < end; j++) {
        int s = __ldg(&g_adj[j]);
        float4 v = __ldg((const float4*)(F + (size_t)s * IND) + ch);
        acc.x += v.x; acc.y += v.y; acc.z += v.z; acc.w += v.w;
    }
    float sc = g_invdeg[node];
    acc.x *= sc; acc.y *= sc; acc.z *= sc; acc.w *= sc;
    *(float4*)(msg12 + (size_t)node * IND + ch * 4) = acc;
}

// ---------------- layer-1 GEMM (K=12, fp32 FFMA) -> buf1 raw1 ----------
#define G12NB 8
__global__ void __launch_bounds__(128)
gemm12_kernel(const float* __restrict__ F) {
    const float* __restrict__ msg12 = g_buf0;  // alias
    __shared__ float W1s[IND * HD], W2s[IND * HD];
    __shared__ float Fs[G12NB][IND], Ms[G12NB][IND];
    int c = threadIdx.x;
    for (int i = c; i < IND * HD; i += 128) { W1s[i] = g_W1c[i]; W2s[i] = g_W2c[i]; }
    float bfx = g_bias1[c], bdg = g_biasd[c];
    int nrow_off = c / IND, kk = c % IND;
    float s = 0.f, s2 = 0.f;
    float* C = g_buf1;
    for (int base = blockIdx.x * G12NB; base < NN; base += gridDim.x * G12NB) {
        __syncthreads();
        if (c < 8 * IND) {
            int n = base + nrow_off;
            Fs[nrow_off][kk] = (n < NN) ? __ldg(&F[(size_t)n * IND + kk]) : 0.f;
            Ms[nrow_off][kk] = (n < NN) ? msg12[(size_t)n * IND + kk] : 0.f;
        }
        __syncthreads();
#pragma unroll
        for (int r = 0; r < G12NB; r++) {
            int n = base + r;
            if (n >= NN) break;
            float acc = bfx + (__ldg(&g_deg[n]) ? bdg : 0.f);
#pragma unroll
            for (int k = 0; k < IND; k++)
                acc += Fs[r][k] * W1s[k * HD + c] + Ms[r][k] * W2s[k * HD + c];
            C[(size_t)n * HD + c] = acc;
            s += acc; s2 += acc * acc;
        }
    }
    atomicAdd(&g_sum[c], s);
    atomicAdd(&g_sqsum[c], s2);
}

// ---------------- CSR gather, plain, 4-neighbor unroll ------------------
__global__ void gather_kernel(int hsel) {
    const float* __restrict__ h = selbuf(hsel);
    float* __restrict__ msg = selbuf(hsel ^ 1);
    int gid = blockIdx.x * blockDim.x + threadIdx.x;
    int node = gid >> 5;
    if (node >= NN) return;
    int lane = gid & 31;
    int beg = __ldg(&g_rowptr[node]);
    int end = __ldg(&g_rowptr[node + 1]);
    float4 acc = make_float4(0.f, 0.f, 0.f, 0.f);
    int j = beg;
    for (; j + 3 < end; j += 4) {
        int s0 = __ldg(&g_adj[j]);
        int s1 = __ldg(&g_adj[j + 1]);
        int s2 = __ldg(&g_adj[j + 2]);
        int s3 = __ldg(&g_adj[j + 3]);
        float4 a = __ldg((const float4*)(h + (size_t)s0 * HD) + lane);
        float4 b = __ldg((const float4*)(h + (size_t)s1 * HD) + lane);
        float4 c = __ldg((const float4*)(h + (size_t)s2 * HD) + lane);
        float4 d = __ldg((const float4*)(h + (size_t)s3 * HD) + lane);
        acc.x += (a.x + b.x) + (c.x + d.x);
        acc.y += (a.y + b.y) + (c.y + d.y);
        acc.z += (a.z + b.z) + (c.z + d.z);
        acc.w += (a.w + b.w) + (c.w + d.w);
    }
    for (; j < end; j++) {
        int s0 = __ldg(&g_adj[j]);
        float4 a = __ldg((const float4*)(h + (size_t)s0 * HD) + lane);
        acc.x += a.x; acc.y += a.y; acc.z += a.z; acc.w += a.w;
    }
    float sc = g_invdeg[node];
    acc.x *= sc; acc.y *= sc; acc.z *= sc; acc.w *= sc;
    ((float4*)(msg + (size_t)node * HD))[lane] = acc;
}

// ---------------- CSR gather with on-the-fly BN+ReLU, 4-unroll ----------
__global__ void gather_bn_kernel(int hsel, int slot) {
    const float* __restrict__ raw = selbuf(hsel);
    float* __restrict__ msg = selbuf(hsel ^ 1);
    int gid = blockIdx.x * blockDim.x + threadIdx.x;
    int node = gid >> 5;
    if (node >= NN) return;
    int lane = gid & 31;
    int c0 = lane * 4;
    float s0c = g_bnsc[slot][c0 + 0], s1c = g_bnsc[slot][c0 + 1];
    float s2c = g_bnsc[slot][c0 + 2], s3c = g_bnsc[slot][c0 + 3];
    float h0c = g_bnsh[slot][c0 + 0], h1c = g_bnsh[slot][c0 + 1];
    float h2c = g_bnsh[slot][c0 + 2], h3c = g_bnsh[slot][c0 + 3];
    int beg = __ldg(&g_rowptr[node]);
    int end = __ldg(&g_rowptr[node + 1]);
    float4 acc = make_float4(0.f, 0.f, 0.f, 0.f);
    int j = beg;
    for (; j + 3 < end; j += 4) {
        int s0 = __ldg(&g_adj[j]);
        int s1 = __ldg(&g_adj[j + 1]);
        int s2 = __ldg(&g_adj[j + 2]);
        int s3 = __ldg(&g_adj[j + 3]);
        float4 a = __ldg((const float4*)(raw + (size_t)s0 * HD) + lane);
        float4 b = __ldg((const float4*)(raw + (size_t)s1 * HD) + lane);
        float4 c = __ldg((const float4*)(raw + (size_t)s2 * HD) + lane);
        float4 d = __ldg((const float4*)(raw + (size_t)s3 * HD) + lane);
        acc.x += fmaxf(a.x * s0c + h0c, 0.f) + fmaxf(b.x * s0c + h0c, 0.f)
               + fmaxf(c.x * s0c + h0c, 0.f) + fmaxf(d.x * s0c + h0c, 0.f);
        acc.y += fmaxf(a.y * s1c + h1c, 0.f) + fmaxf(b.y * s1c + h1c, 0.f)
               + fmaxf(c.y * s1c + h1c, 0.f) + fmaxf(d.y * s1c + h1c, 0.f);
        acc.z += fmaxf(a.z * s2c + h2c, 0.f) + fmaxf(b.z * s2c + h2c, 0.f)
               + fmaxf(c.z * s2c + h2c, 0.f) + fmaxf(d.z * s2c + h2c, 0.f);
        acc.w += fmaxf(a.w * s3c + h3c, 0.f) + fmaxf(b.w * s3c + h3c, 0.f)
               + fmaxf(c.w * s3c + h3c, 0.f) + fmaxf(d.w * s3c + h3c, 0.f);
    }
    for (; j < end; j++) {
        int s = __ldg(&g_adj[j]);
        float4 a = __ldg((const float4*)(raw + (size_t)s * HD) + lane);
        acc.x += fmaxf(a.x * s0c + h0c, 0.f);
        acc.y += fmaxf(a.y * s1c + h1c, 0.f);
        acc.z += fmaxf(a.z * s2c + h2c, 0.f);
        acc.w += fmaxf(a.w * s3c + h3c, 0.f);
    }
    float sc = g_invdeg[node];
    acc.x *= sc; acc.y *= sc; acc.z *= sc; acc.w *= sc;
    ((float4*)(msg + (size_t)node * HD))[lane] = acc;
}

// ---------------- fused dual GEMM (tf32, BK=16, prefetched tiles) -------
#define BM 128
#define BK 16
#define ALD (BK + 4)
#define BLD (HD + 4)
#define WTLD 20
__global__ void __launch_bounds__(256)
gemm_layer_kernel(int hsel, int bnslot,
                  const float* __restrict__ Wsp,
                  const float* __restrict__ Wnp,
                  const float* __restrict__ bias) {
    __shared__ float As[BM * ALD];
    __shared__ float Bs[BK * BLD];
    __shared__ float wtile[8][16 * WTLD];
    __shared__ float colsum[HD], colsq[HD];
    __shared__ float bsc[HD], bsh[HD];

    const float* A1 = selbuf(hsel);
    float* Msg = selbuf(hsel ^ 1);
    float* C = Msg;  // in-place
    const int nrows = NN;
    int tid = threadIdx.x;
    int w = tid >> 5, lane = tid & 31;
    int wm = w & 3, wn = w >> 2;
    int row0 = blockIdx.x * BM;

    if (tid < HD) {
        colsum[tid] = 0.f; colsq[tid] = 0.f;
        if (bnslot >= 0) { bsc[tid] = g_bnsc[bnslot][tid]; bsh[tid] = g_bnsh[bnslot][tid]; }
    }

    int am0 = (tid * 2) >> 2,     ak0 = ((tid * 2) & 3) * 4;
    int am1 = (tid * 2 + 1) >> 2, ak1 = ((tid * 2 + 1) & 3) * 4;
    int arc0 = (row0 + am0) < nrows ? (row0 + am0) : nrows - 1;
    int arc1 = (row0 + am1) < nrows ? (row0 + am1) : nrows - 1;
    int wk0 = (tid * 2) >> 5,     wc0 = ((tid * 2) & 31) * 4;
    int wk1 = (tid * 2 + 1) >> 5, wc1 = ((tid * 2 + 1) & 31) * 4;

    wmma::fragment<wmma::accumulator, 16, 16, 8, float> acc[2][4];
#pragma unroll
    for (int i = 0; i < 2; i++)
#pragma unroll
        for (int j = 0; j < 4; j++) wmma::fill_fragment(acc[i][j], 0.f);

    for (int pass = 0; pass < 2; ++pass) {
        const float* A = pass ? Msg : A1;
        const float* W = pass ? Wnp : Wsp;
        int abn = (pass == 0 && bnslot >= 0);
        for (int k0 = 0; k0 < HD; k0 += BK) {
            float4 va0 = __ldg((const float4*)(A + (size_t)arc0 * HD + k0 + ak0));
            float4 va1 = __ldg((const float4*)(A + (size_t)arc1 * HD + k0 + ak1));
            float4 vw0 = __ldg((const float4*)(W + (size_t)(k0 + wk0) * HD + wc0));
            float4 vw1 = __ldg((const float4*)(W + (size_t)(k0 + wk1) * HD + wc1));
            __syncthreads();
            if (abn) {
                va0.x = fmaxf(va0.x * bsc[k0 + ak0 + 0] + bsh[k0 + ak0 + 0], 0.f);
                va0.y = fmaxf(va0.y * bsc[k0 + ak0 + 1] + bsh[k0 + ak0 + 1], 0.f);
                va0.z = fmaxf(va0.z * bsc[k0 + ak0 + 2] + bsh[k0 + ak0 + 2], 0.f);
                va0.w = fmaxf(va0.w * bsc[k0 + ak0 + 3] + bsh[k0 + ak0 + 3], 0.f);
                va1.x = fmaxf(va1.x * bsc[k0 + ak1 + 0] + bsh[k0 + ak1 + 0], 0.f);
                va1.y = fmaxf(va1.y * bsc[k0 + ak1 + 1] + bsh[k0 + ak1 + 1], 0.f);
                va1.z = fmaxf(va1.z * bsc[k0 + ak1 + 2] + bsh[k0 + ak1 + 2], 0.f);
                va1.w = fmaxf(va1.w * bsc[k0 + ak1 + 3] + bsh[k0 + ak1 + 3], 0.f);
            }
            As[am0 * ALD + ak0 + 0] = wmma::__float_to_tf32(va0.x);
            As[am0 * ALD + ak0 + 1] = wmma::__float_to_tf32(va0.y);
            As[am0 * ALD + ak0 + 2] = wmma::__float_to_tf32(va0.z);
            As[am0 * ALD + ak0 + 3] = wmma::__float_to_tf32(va0.w);
            As[am1 * ALD + ak1 + 0] = wmma::__float_to_tf32(va1.x);
            As[am1 * ALD + ak1 + 1] = wmma::__float_to_tf32(va1.y);
            As[am1 * ALD + ak1 + 2] = wmma::__float_to_tf32(va1.z);
            As[am1 * ALD + ak1 + 3] = wmma::__float_to_tf32(va1.w);
            Bs[wk0 * BLD + wc0 + 0] = wmma::__float_to_tf32(vw0.x);
            Bs[wk0 * BLD + wc0 + 1] = wmma::__float_to_tf32(vw0.y);
            Bs[wk0 * BLD + wc0 + 2] = wmma::__float_to_tf32(vw0.z);
            Bs[wk0 * BLD + wc0 + 3] = wmma::__float_to_tf32(vw0.w);
            Bs[wk1 * BLD + wc1 + 0] = wmma::__float_to_tf32(vw1.x);
            Bs[wk1 * BLD + wc1 + 1] = wmma::__float_to_tf32(vw1.y);
            Bs[wk1 * BLD + wc1 + 2] = wmma::__float_to_tf32(vw1.z);
            Bs[wk1 * BLD + wc1 + 3] = wmma::__float_to_tf32(vw1.w);
            __syncthreads();
#pragma unroll
            for (int ks = 0; ks < BK; ks += 8) {
                wmma::fragment<wmma::matrix_a, 16, 16, 8, wmma::precision::tf32, wmma::row_major> af[2];
                wmma::fragment<wmma::matrix_b, 16, 16, 8, wmma::precision::tf32, wmma::row_major> bf[4];
#pragma unroll
                for (int i = 0; i < 2; i++)
                    wmma::load_matrix_sync(af[i], &As[(wm * 32 + i * 16) * ALD + ks], ALD);
#pragma unroll
                for (int j = 0; j < 4; j++)
                    wmma::load_matrix_sync(bf[j], &Bs[ks * BLD + wn * 64 + j * 16], BLD);
#pragma unroll
                for (int i = 0; i < 2; i++)
#pragma unroll
                    for (int j = 0; j < 4; j++)
                        wmma::mma_sync(acc[i][j], af[i], bf[j], acc[i][j]);
            }
        }
    }

    float* wt = wtile[w];
    int cl = lane & 15;
    int rh = lane >> 4;
#pragma unroll
    for (int i = 0; i < 2; i++) {
#pragma unroll
        for (int j = 0; j < 4; j++) {
            wmma::store_matrix_sync(wt, acc[i][j], WTLD, wmma::mem_row_major);
            __syncwarp();
            int gc = wn * 64 + j * 16 + cl;
            int rbase = row0 + wm * 32 + i * 16 + rh * 8;
            float bia = bias[gc];
            float s = 0.f, s2 = 0.f;
#pragma unroll
            for (int r = 0; r < 8; r++) {
                int gr = rbase + r;
                float v = wt[(rh * 8 + r) * WTLD + cl] + bia;
                if (gr < nrows) {
                    C[(size_t)gr * HD + gc] = v;
                    s += v;
                    s2 += v * v;
                }
            }
            s  += __shfl_down_sync(0xffffffffu, s, 16);
            s2 += __shfl_down_sync(0xffffffffu, s2, 16);
            if (lane < 16) {
                atomicAdd(&colsum[gc], s);
                atomicAdd(&colsq[gc], s2);
            }
            __syncwarp();
        }
    }
    __syncthreads();
    if (tid < HD) {
        atomicAdd(&g_sum[tid], colsum[tid]);
        atomicAdd(&g_sqsum[tid], colsq[tid]);
    }
}

// ---------------- BN finalize into slot (+self-reset) ------------------
__global__ void bn_finalize_kernel(const float* __restrict__ gamma,
                                   const float* __restrict__ beta, int slot) {
    int c = threadIdx.x;
    float mu = g_sum[c] * (1.0f / NN);
    float var = g_sqsum[c] * (1.0f / NN) - mu * mu;
    float r = rsqrtf(var + BNEPS);
    float a = gamma[c] * r;
    g_bnsc[slot][c] = a;
    g_bnsh[slot][c] = beta[c] - mu * a;
    g_sum[c] = 0.f;
    g_sqsum[c] = 0.f;
}

// ---------------- layer-2 act: h2 = relu(bn1(raw2)) + relu(bn0(raw1)) --
__global__ void bn_apply2_kernel() {
    float* X = g_buf0;                // raw2 -> h2 (in place)
    const float* Res = g_buf1;        // raw1
    int i = blockIdx.x * blockDim.x + threadIdx.x;
    int total4 = NN * HD / 4;
    if (i >= total4) return;
    int c = (i & 31) * 4;
    float4 v = ((float4*)X)[i];
    float4 r = ((const float4*)Res)[i];
    v.x = fmaxf(v.x * g_bnsc[1][c+0] + g_bnsh[1][c+0], 0.f) + fmaxf(r.x * g_bnsc[0][c+0] + g_bnsh[0][c+0], 0.f);
    v.y = fmaxf(v.y * g_bnsc[1][c+1] + g_bnsh[1][c+1], 0.f) + fmaxf(r.y * g_bnsc[0][c+1] + g_bnsh[0][c+1], 0.f);
    v.z = fmaxf(v.z * g_bnsc[1][c+2] + g_bnsh[1][c+2], 0.f) + fmaxf(r.z * g_bnsc[0][c+2] + g_bnsh[0][c+2], 0.f);
    v.w = fmaxf(v.w * g_bnsc[1][c+3] + g_bnsh[1][c+3], 0.f) + fmaxf(r.w * g_bnsc[0][c+3] + g_bnsh[0][c+3], 0.f);
    ((float4*)X)[i] = v;
}

// ---------------- tensor-core head ----------------
// h3[n] = relu(bn0(raw3[n])) + h2[n]  (fused into A-tile load)
// hid = relu(h3 @ W1 + b1)  (tf32 wmma, [128-tile,64])
// out = hid @ W2 + b2       (per-warp smem epilogue, cross-warp partials)
#define HALD 20          // A-tile ld (BK=16 + 4)
#define HBLD 68          // W1-tile ld (64 + 4)
#define HWT  36          // per-warp 16x32 staging ld (144 B, x16 OK)
__global__ void __launch_bounds__(256)
head_kernel(const float* __restrict__ W1,
            const float* __restrict__ b1,
            const float* __restrict__ W2,
            const float* __restrict__ b2,
            float* __restrict__ out) {
    const float* Raw = g_buf1;        // raw3
    const float* Res = g_buf0;        // h2
    __shared__ float As[BM * HALD];       // 10240 B
    __shared__ float Bs[16 * HBLD];       // 4352 B
    __shared__ float wt2[8][16 * HWT];    // 18432 B
    __shared__ float part[BM][4];         // 2048 B
    __shared__ float bsc[HD], bsh[HD];    // 1024 B
    __shared__ float b1s[64], w2s[128];   // 768 B

    int tid = threadIdx.x;
    int w = tid >> 5, lane = tid & 31;
    int wm = w & 3, wn = w >> 2;          // 4(M) x 2(N); each warp 32x32 out
    int row0 = blockIdx.x * BM;

    if (tid < HD) { bsc[tid] = g_bnsc[0][tid]; bsh[tid] = g_bnsh[0][tid]; }
    if (tid < 64) b1s[tid] = b1[tid];
    if (tid < 128) w2s[tid] = W2[tid];

    int am0 = (tid * 2) >> 2,     ak0 = ((tid * 2) & 3) * 4;
    int am1 = (tid * 2 + 1) >> 2, ak1 = ((tid * 2 + 1) & 3) * 4;
    int arc0 = (row0 + am0) < NN ? (row0 + am0) : NN - 1;
    int arc1 = (row0 + am1) < NN ? (row0 + am1) : NN - 1;
    int wk = tid >> 4, wc = (tid & 15) * 4;   // W1 tile: 16x64, 1 float4/thread

    wmma::fragment<wmma::accumulator, 16, 16, 8, float> acc[2][2];
#pragma unroll
    for (int i = 0; i < 2; i++)
#pragma unroll
        for (int j = 0; j < 2; j++) wmma::fill_fragment(acc[i][j], 0.f);

    for (int k0 = 0; k0 < HD; k0 += 16) {
        float4 va0 = __ldg((const float4*)(Raw + (size_t)arc0 * HD + k0 + ak0));
        float4 vr0 = __ldg((const float4*)(Res + (size_t)arc0 * HD + k0 + ak0));
        float4 va1 = __ldg((const float4*)(Raw + (size_t)arc1 * HD + k0 + ak1));
        float4 vr1 = __ldg((const float4*)(Res + (size_t)arc1 * HD + k0 + ak1));
        float4 vw = __ldg((const float4*)(W1 + (size_t)(k0 + wk) * 64 + wc));
        __syncthreads();
        va0.x = fmaxf(va0.x * bsc[k0 + ak0 + 0] + bsh[k0 + ak0 + 0], 0.f) + vr0.x;
        va0.y = fmaxf(va0.y * bsc[k0 + ak0 + 1] + bsh[k0 + ak0 + 1], 0.f) + vr0.y;
        va0.z = fmaxf(va0.z * bsc[k0 + ak0 + 2] + bsh[k0 + ak0 + 2], 0.f) + vr0.z;
        va0.w = fmaxf(va0.w * bsc[k0 + ak0 + 3] + bsh[k0 + ak0 + 3], 0.f) + vr0.w;
        va1.x = fmaxf(va1.x * bsc[k0 + ak1 + 0] + bsh[k0 + ak1 + 0], 0.f) + vr1.x;
        va1.y = fmaxf(va1.y * bsc[k0 + ak1 + 1] + bsh[k0 + ak1 + 1], 0.f) + vr1.y;
        va1.z = fmaxf(va1.z * bsc[k0 + ak1 + 2] + bsh[k0 + ak1 + 2], 0.f) + vr1.z;
        va1.w = fmaxf(va1.w * bsc[k0 + ak1 + 3] + bsh[k0 + ak1 + 3], 0.f) + vr1.w;
        As[am0 * HALD + ak0 + 0] = wmma::__float_to_tf32(va0.x);
        As[am0 * HALD + ak0 + 1] = wmma::__float_to_tf32(va0.y);
        As[am0 * HALD + ak0 + 2] = wmma::__float_to_tf32(va0.z);
        As[am0 * HALD + ak0 + 3] = wmma::__float_to_tf32(va0.w);
        As[am1 * HALD + ak1 + 0] = wmma::__float_to_tf32(va1.x);
        As[am1 * HALD + ak1 + 1] = wmma::__float_to_tf32(va1.y);
        As[am1 * HALD + ak1 + 2] = wmma::__float_to_tf32(va1.z);
        As[am1 * HALD + ak1 + 3] = wmma::__float_to_tf32(va1.w);
        Bs[wk * HBLD + wc + 0] = wmma::__float_to_tf32(vw.x);
        Bs[wk * HBLD + wc + 1] = wmma::__float_to_tf32(vw.y);
        Bs[wk * HBLD + wc + 2] = wmma::__float_to_tf32(vw.z);
        Bs[wk * HBLD + wc + 3] = wmma::__float_to_tf32(vw.w);
        __syncthreads();
#pragma unroll
        for (int ks = 0; ks < 16; ks += 8) {
            wmma::fragment<wmma::matrix_a, 16, 16, 8, wmma::precision::tf32, wmma::row_major> af[2];
            wmma::fragment<wmma::matrix_b, 16, 16, 8, wmma::precision::tf32, wmma::row_major> bf[2];
#pragma unroll
            for (int i = 0; i < 2; i++)
                wmma::load_matrix_sync(af[i], &As[(wm * 32 + i * 16) * HALD + ks], HALD);
#pragma unroll
            for (int j = 0; j < 2; j++)
                wmma::load_matrix_sync(bf[j], &Bs[ks * HBLD + wn * 32 + j * 16], HBLD);
#pragma unroll
            for (int i = 0; i < 2; i++)
#pragma unroll
                for (int j = 0; j < 2; j++)
                    wmma::mma_sync(acc[i][j], af[i], bf[j], acc[i][j]);
        }
    }

    // Epilogue: per-warp relu(.+b1) then dot with W2 over the warp's 32 cols.
    float* wt = wt2[w];
    int rr = lane >> 1, hh = lane & 1;     // 16 rows x 2 col-halves
#pragma unroll
    for (int i = 0; i < 2; i++) {
        wmma::store_matrix_sync(wt,      acc[i][0], HWT, wmma::mem_row_major);
        wmma::store_matrix_sync(wt + 16, acc[i][1], HWT, wmma::mem_row_major);
        __syncwarp();
        float o0 = 0.f, o1 = 0.f;
#pragma unroll
        for (int c = 0; c < 16; c++) {
            int col = hh * 16 + c;
            int gcol = wn * 32 + col;
            float v = fmaxf(wt[rr * HWT + col] + b1s[gcol], 0.f);
            o0 += v * w2s[gcol * 2 + 0];
            o1 += v * w2s[gcol * 2 + 1];
        }
        o0 += __shfl_xor_sync(0xffffffffu, o0, 1);
        o1 += __shfl_xor_sync(0xffffffffu, o1, 1);
        if (hh == 0) {
            int lr = wm * 32 + i * 16 + rr;
            part[lr][wn * 2 + 0] = o0;
            part[lr][wn * 2 + 1] = o1;
        }
        __syncwarp();
    }
    __syncthreads();
    if (tid < BM) {
        int gr = row0 + tid;
        if (gr < NN) {
            out[gr * 2 + 0] = part[tid][0] + part[tid][2] + b2[0];
            out[gr * 2 + 1] = part[tid][1] + part[tid][3] + b2[1];
        }
    }
}

// ---------------- launch (kernel launches ONLY) ----------------
extern "C" void kernel_launch(void* const* d_in, const int* in_sizes, int n_in,
                              void* d_out, int out_size) {
    const float* features = (const float*)d_in[0];
    const void*  edge     = d_in[1];
    const float* emb_W    = (const float*)d_in[2];
    const float* emb_b    = (const float*)d_in[3];
    const float* Wself    = (const float*)d_in[4];
    const float* Wneigh   = (const float*)d_in[5];
    const float* conv_b   = (const float*)d_in[6];
    const float* gamma    = (const float*)d_in[7];
    const float* beta     = (const float*)d_in[8];
    const float* W1       = (const float*)d_in[9];
    const float* b1       = (const float*)d_in[10];
    const float* W2       = (const float*)d_in[11];
    const float* b2       = (const float*)d_in[12];
    float* out = (float*)d_out;

    zero_kernel<<<(NN + 255) / 256, 256>>>();
    extract_count_kernel<<<(2 * EE + 255) / 256, 256>>>(edge);
    prep_weights_kernel<<<dim3(IND + 1, 4), 128>>>(emb_W, emb_b, Wself, Wneigh, conv_b);
    blocksum_kernel<<<NSCAN, SCB>>>();
    scan_bsum_kernel<<<1, 128>>>();
    fill_rowptr_kernel<<<NSCAN, SCB>>>();
    place_edges_kernel<<<(EE + 255) / 256, 256>>>();

    // ---- layer 1 in 12-dim space ----
    gather12_kernel<<<(NN * 4 + 255) / 256, 256>>>(features);   // msg12 -> buf0 alias
    gemm12_kernel<<<1024, 128>>>(features);                     // -> buf1 raw1 + stats
    bn_finalize_kernel<<<1, HD>>>(gamma, beta, 0);              // BN1 -> slot 0

    // ---- layer 2 (h1 never materialized; BN1 applied on the fly) ----
    gather_bn_kernel<<<(NN * 32 + 255) / 256, 256>>>(1, 0);     // raw1(buf1) -> msg(buf0)
    gemm_layer_kernel<<<(NN + BM - 1) / BM, 256>>>(
        1, 0, Wself + (size_t)1 * HD * HD, Wneigh + (size_t)1 * HD * HD,
        conv_b + 1 * HD);                                        // -> buf0 raw2
    bn_finalize_kernel<<<1, HD>>>(gamma + 1 * HD, beta + 1 * HD, 1);  // BN2 -> slot 1
    bn_apply2_kernel<<<(NN * HD / 4 + 255) / 256, 256>>>();     // buf0 = h2

    // ---- layer 3 ----
    gather_kernel<<<(NN * 32 + 255) / 256, 256>>>(0);           // h2(buf0) -> msg(buf1)
    gemm_layer_kernel<<<(NN + BM - 1) / BM, 256>>>(
        0, -1, Wself + (size_t)2 * HD * HD, Wneigh + (size_t)2 * HD * HD,
        conv_b + 2 * HD);                                        // -> buf1 raw3
    bn_finalize_kernel<<<1, HD>>>(gamma + 2 * HD, beta + 2 * HD, 0);  // BN3 -> slot 0
    head_kernel<<<(NN + BM - 1) / BM, 256>>>(W1, b1, W2, b2, out);   // raw3+h2 -> out
}